// round 15
// baseline (speedup 1.0000x reference)
#include <cuda_runtime.h>
#include <cuda_fp16.h>
#include <cstdint>

#define NB 8
#define HGT 60
#define WID 80
#define PP (NB*HGT*WID)   // 38400 positions

// ---------------- static scratch ----------------
__device__ __half g_x1[(size_t)PP*512];
__device__ __half g_ya[(size_t)PP*256];
__device__ __half g_yb[(size_t)PP*256];
__device__ __half g_gxh[(size_t)PP*1024];
__device__ __half g_bmat[(size_t)1280*1024];
__device__ __half g_wrec[(size_t)4*2*512*128];
__device__ float  g_scp[4*8*1024];
__device__ float  g_sc1[8*512];
__device__ float  g_scr[8*256];
__device__ float  g_score[PP];

// ---------------- helpers ----------------
__device__ __forceinline__ float tanhfast(float x){
  float y; asm("tanh.approx.f32 %0, %1;" : "=f"(y) : "f"(x)); return y;
}
__device__ __forceinline__ __half2 tanh2(__half2 x){
  uint32_t y, xi = *(uint32_t*)&x;
  asm("tanh.approx.f16x2 %0, %1;" : "=r"(y) : "r"(xi));
  return *(__half2*)&y;
}
__device__ __forceinline__ float sigm(float x){ return __fdividef(1.f, 1.f + __expf(-x)); }

__device__ __forceinline__ void ldsm4(uint32_t* r, const void* p){
  uint32_t a = (uint32_t)__cvta_generic_to_shared(p);
  asm volatile("ldmatrix.sync.aligned.m8n8.x4.shared.b16 {%0,%1,%2,%3}, [%4];\n"
    : "=r"(r[0]),"=r"(r[1]),"=r"(r[2]),"=r"(r[3]) : "r"(a));
}
__device__ __forceinline__ void ldsm4t(uint32_t* r, const void* p){
  uint32_t a = (uint32_t)__cvta_generic_to_shared(p);
  asm volatile("ldmatrix.sync.aligned.m8n8.x4.trans.shared.b16 {%0,%1,%2,%3}, [%4];\n"
    : "=r"(r[0]),"=r"(r[1]),"=r"(r[2]),"=r"(r[3]) : "r"(a));
}
__device__ __forceinline__ void mma16816(float* c, const uint32_t* a, uint32_t b0, uint32_t b1){
  asm volatile(
    "mma.sync.aligned.m16n8k16.row.col.f32.f16.f16.f32 "
    "{%0,%1,%2,%3}, {%4,%5,%6,%7}, {%8,%9}, {%0,%1,%2,%3};\n"
    : "+f"(c[0]), "+f"(c[1]), "+f"(c[2]), "+f"(c[3])
    : "r"(a[0]), "r"(a[1]), "r"(a[2]), "r"(a[3]), "r"(b0), "r"(b1));
}
__device__ __forceinline__ void mma16816h(uint32_t* c, const uint32_t* a, uint32_t b0, uint32_t b1){
  asm volatile(
    "mma.sync.aligned.m16n8k16.row.col.f16.f16.f16.f16 "
    "{%0,%1}, {%2,%3,%4,%5}, {%6,%7}, {%0,%1};\n"
    : "+r"(c[0]), "+r"(c[1])
    : "r"(a[0]), "r"(a[1]), "r"(a[2]), "r"(a[3]), "r"(b0), "r"(b1));
}
__device__ __forceinline__ void cpasync16(void* smem, const void* g){
  uint32_t a = (uint32_t)__cvta_generic_to_shared(smem);
  asm volatile("cp.async.cg.shared.global [%0], [%1], 16;\n" :: "r"(a), "l"(g));
}
__device__ __forceinline__ void cp_commit(){ asm volatile("cp.async.commit_group;\n"); }
template<int N> __device__ __forceinline__ void cp_wait(){
  asm volatile("cp.async.wait_group %0;\n" :: "n"(N));
}
__device__ __forceinline__ const __half* pick_x(int s){
  return s==0 ? g_x1 : (s==1 ? g_ya : g_yb);
}
__device__ __forceinline__ __half* pick_y(int s){
  return s==1 ? g_ya : g_yb;
}

// ---------------- merged prep ----------------
__global__ __launch_bounds__(256) void k_prep_all(
    const float* __restrict__ scene,
    const float* __restrict__ fc1w, const float* __restrict__ fc1b,
    const float* __restrict__ fcrw, const float* __restrict__ fcrb,
    const float* __restrict__ w0, const float* __restrict__ w1,
    const float* __restrict__ w2, const float* __restrict__ w3,
    const float* __restrict__ h0, const float* __restrict__ h1,
    const float* __restrict__ h2, const float* __restrict__ h3,
    const float* __restrict__ lf){
  __shared__ float smu[32*33];
  const int b = blockIdx.x, tid = threadIdx.x;
  if (b < 96){
    float (*s)[128] = (float(*)[128])smu;
    int lane = tid & 31, wp = tid >> 5;
    for (int i = tid; i < 1024; i += 256) s[i>>7][i&127] = scene[i];
    __syncthreads();
    int o = b*8 + wp;
    const float* wrow; float bb; float* outp; int stride;
    if (o < 512){ wrow = fc1w + o*128; bb = fc1b[o]; outp = g_sc1 + o; stride = 512; }
    else { int oo = o-512; wrow = fcrw + oo*128; bb = fcrb[oo]; outp = g_scr + oo; stride = 256; }
    float q0 = wrow[lane], q1 = wrow[32+lane], q2 = wrow[64+lane], q3 = wrow[96+lane];
    #pragma unroll
    for (int n=0;n<8;n++){
      float p = q0*s[n][lane] + q1*s[n][32+lane] + q2*s[n][64+lane] + q3*s[n][96+lane];
      #pragma unroll
      for (int d=16;d;d>>=1) p += __shfl_xor_sync(0xffffffffu, p, d);
      if (lane == 0) outp[n*stride] = p + bb;
    }
  } else if (b < 1376){
    int id = b - 96, L, kx, cx;
    if (id < 512){ L = 0; kx = id >> 5; cx = id & 31; }
    else { id -= 512; L = 1 + id/256; int rr = id % 256; kx = rr >> 5; cx = rr & 31; }
    const int I = (L==0) ? 512 : 256;
    const float* wih = (L==0) ? w0 : (L==1) ? w1 : (L==2) ? w2 : w3;
    const size_t bmoff = (L==0) ? 0 : (size_t)(256 + 256*L)*1024;
    float (*tile)[33] = (float(*)[33])smu;
    int tx = tid & 31, ty = tid >> 5;
    int k0 = kx*32, c0 = cx*32;
    #pragma unroll
    for (int i=0;i<4;i++)
      tile[ty + i*8][tx] = wih[(size_t)(c0 + ty + i*8)*I + k0 + tx];
    __syncthreads();
    #pragma unroll
    for (int i=0;i<4;i++)
      g_bmat[bmoff + (size_t)(k0 + ty + i*8)*1024 + c0 + tx] = __float2half(tile[tx][ty + i*8]);
  } else if (b < 3424){
    int id = (b - 1376)*256 + tid;
    int L = id >> 17, r = id & 131071;
    const float* src = (L==0) ? h0 : (L==1) ? h1 : (L==2) ? h2 : h3;
    g_wrec[id] = __float2half(src[r]);
  } else {
    int id = b - 3424;
    int p0 = (id % 150)*32, c0 = ((id/150) & 15)*32, n = id/2400;
    float (*tile)[33] = (float(*)[33])smu;
    int tx = tid & 31, ty = tid >> 5;
    #pragma unroll
    for (int i=0;i<4;i++)
      tile[ty + i*8][tx] = lf[((size_t)(n*512 + c0 + ty + i*8))*4800 + p0 + tx];
    __syncthreads();
    #pragma unroll
    for (int i=0;i<4;i++)
      g_x1[((size_t)(n*4800 + p0 + ty + i*8))*512 + c0 + tx] = __float2half(tile[tx][ty + i*8]);
  }
}

// scene-context projection, all 4 layers
__global__ __launch_bounds__(256) void k_scproj_all(
    const float* __restrict__ w0, const float* __restrict__ w1,
    const float* __restrict__ w2, const float* __restrict__ w3){
  __shared__ float s[8*512];
  const int L = blockIdx.y;
  const int I = (L==0) ? 512 : 256;
  const float* wih = (L==0) ? w0 : (L==1) ? w1 : (L==2) ? w2 : w3;
  const float* scsrc = (L==0) ? g_sc1 : g_scr;
  int tid = threadIdx.x, lane = tid & 31, wp = tid >> 5;
  for (int i = tid; i < 8*I; i += 256) s[i] = scsrc[i];
  __syncthreads();
  for (int c = wp; c < 32; c += 8){
    int col = blockIdx.x*32 + c;
    const float* wr = wih + (size_t)col * I;
    float w[16];
    #pragma unroll
    for (int i=0;i<16;i++) w[i] = (i*32 < I) ? wr[lane + i*32] : 0.f;
    #pragma unroll
    for (int n=0;n<8;n++){
      float p = 0.f;
      #pragma unroll
      for (int i=0;i<16;i++) if (i*32 < I) p += w[i]*s[n*I + lane + i*32];
      #pragma unroll
      for (int d=16;d;d>>=1) p += __shfl_xor_sync(0xffffffffu, p, d);
      if (lane == 0) g_scp[L*8192 + n*1024 + col] = p;
    }
  }
}

// ---------------- input-projection GEMM ----------------
// MODE 1: fp16 acc, single group (K<=256). MODE 2: fp16 acc, two K-groups summed in f32.
#define AS_OFF(buf) ((buf)*9216)
#define BS_OFF(buf) (18432 + (buf)*8704)
#define GEMM_SMEM ((18432 + 2*8704)*2)

template<int MODE>
__global__ __launch_bounds__(256) void k_gemm_proj(
    int xsel, int bmoff, const float* __restrict__ bias, int scpoff,
    int I, int scan_type){
  extern __shared__ __half sm[];
  const __half* __restrict__ X = pick_x(xsel);
  const __half* __restrict__ Bm = g_bmat + (size_t)bmoff;
  const int tid = threadIdx.x, lane = tid & 31, wp = tid >> 5;
  const int wm = wp & 3, wn = wp >> 2;
  const int m0 = blockIdx.x * 128, n0 = blockIdx.y * 128;
  const int nch = I >> 6;
  uint32_t acch[2][2][8][2];   // [group][mt][nt][d]; group 1 unused when MODE==1
  #pragma unroll
  for (int g=0;g<((MODE==2)?2:1);g++)
    #pragma unroll
    for (int a=0;a<2;a++)
      #pragma unroll
      for (int b=0;b<8;b++){ acch[g][a][b][0]=0u; acch[g][a][b][1]=0u; }

  auto stage = [&](int c, int buf){
    int k0 = c*64;
    __half* as = sm + AS_OFF(buf);
    __half* bs = sm + BS_OFF(buf);
    #pragma unroll
    for (int i=0;i<4;i++){
      int idx = tid + i*256;
      int r = idx >> 3, cb = (idx & 7) * 8;
      cpasync16(&as[r*72 + cb], &X[(size_t)(m0 + r) * I + k0 + cb]);
    }
    #pragma unroll
    for (int i=0;i<4;i++){
      int idx = tid + i*256;
      int r = idx >> 4, cb = (idx & 15) * 8;
      cpasync16(&bs[r*136 + cb], &Bm[(size_t)(k0 + r) * 1024 + n0 + cb]);
    }
    cp_commit();
  };

  stage(0, 0);
  if (nch > 1) stage(1, 1);

  for (int c = 0; c < nch; ++c){
    if (c+1 < nch) cp_wait<1>(); else cp_wait<0>();
    __syncthreads();
    const int grp = (MODE==2 && c >= (nch>>1)) ? 1 : 0;
    const __half* as = sm + AS_OFF(c & 1);
    const __half* bs = sm + BS_OFF(c & 1);
    #pragma unroll
    for (int kc=0;kc<4;kc++){
      uint32_t a[2][4];
      #pragma unroll
      for (int mt=0;mt<2;mt++){
        int row = wm*32 + mt*16 + ((lane>>3)&1)*8 + (lane&7);
        int col = kc*16 + (lane>>4)*8;
        ldsm4(a[mt], &as[row*72 + col]);
      }
      #pragma unroll
      for (int p=0;p<4;p++){
        uint32_t b[4];
        int row = kc*16 + ((lane>>3)&1)*8 + (lane&7);
        int col = wn*64 + p*16 + (lane>>4)*8;
        ldsm4t(b, &bs[row*136 + col]);
        #pragma unroll
        for (int mt=0;mt<2;mt++){
          mma16816h(acch[grp][mt][2*p],   a[mt], b[0], b[1]);
          mma16816h(acch[grp][mt][2*p+1], a[mt], b[2], b[3]);
        }
      }
    }
    __syncthreads();
    if (c+2 < nch) stage(c+2, c & 1);
  }

  const int r0 = lane >> 2, cc0 = (lane & 3) * 2;
  const float* scp = g_scp + scpoff;
  #pragma unroll
  for (int mt=0; mt<2; mt++)
    #pragma unroll
    for (int hf=0; hf<2; hf++){
      int m = m0 + wm*32 + mt*16 + hf*8 + r0;
      bool bnd;
      if (scan_type==0){ int wv = m % 80; bnd = (wv==0)||(wv==79); }
      else { int hv = (m/80)%60; bnd = (hv==0)||(hv==59); }
      const float* sp = scp + (m/4800)*1024;
      #pragma unroll
      for (int nt=0;nt<8;nt++){
        int c = n0 + wn*64 + nt*8 + cc0;
        float2 f = __half22float2(*(__half2*)&acch[0][mt][nt][hf]);
        float v0 = f.x, v1 = f.y;
        if (MODE==2){
          float2 f2 = __half22float2(*(__half2*)&acch[1][mt][nt][hf]);
          v0 += f2.x; v1 += f2.y;
        }
        v0 += bias[c]; v1 += bias[c+1];
        if (bnd){ v0 += sp[c]; v1 += sp[c+1]; }
        *(__half2*)&g_gxh[(size_t)m*1024 + c] = __floats2half2_rn(v0, v1);
      }
    }
}

// ---------------- persistent BLSTM scan: f16x2 activations ----------------
__global__ __launch_bounds__(512) void k_scan(
    int layer, int ysel, int scan_type, int T, int bpd, int S){
  __shared__ __half hsm[2][16][136];
  __shared__ __half gxs[2][16][520];
  __half* __restrict__ yout = pick_y(ysel);
  const int tid = threadIdx.x, lane = tid & 31, wp = tid >> 5;
  const int dir = blockIdx.x / bpd;
  const int s0 = (blockIdx.x % bpd) * S;
  const __half* __restrict__ wd = g_wrec + (size_t)layer*131072 + (size_t)dir*65536;

  uint32_t bf[8][4][2];
  #pragma unroll
  for (int kc=0;kc<8;kc++)
    #pragma unroll
    for (int nt=0;nt<4;nt++){
      int n = nt*128 + wp*8 + (lane>>2);
      int k = kc*16 + (lane&3)*2;
      bf[kc][nt][0] = *(const uint32_t*)&wd[(size_t)n*128 + k];
      bf[kc][nt][1] = *(const uint32_t*)&wd[(size_t)n*128 + k + 8];
    }

  for (int i = tid; i < 2*16*136; i += 512) ((__half*)hsm)[i] = __ushort_as_half((unsigned short)0);

  const int r  = lane >> 2;
  const int ul = (lane & 3) * 2;
  const int col = wp*8 + ul;
  const bool act2 = (r + 8) < S;
  int pstride = (scan_type == 0) ? 1 : 80;
  size_t posbase1 = 0, posbase2 = 0;
  {
    int s = s0 + r;
    posbase1 = (scan_type==0) ? (size_t)s*80 : (size_t)(s/80)*4800 + (s%80);
    if (act2){
      int s2 = s0 + r + 8;
      posbase2 = (scan_type==0) ? (size_t)s2*80 : (size_t)(s2/80)*4800 + (s2%80);
    }
  }
  const int crow = tid >> 6;
  const int cch  = tid & 63;
  const bool cv1 = (crow + 8) < S;
  size_t cpb0, cpb1 = 0;
  {
    int s = s0 + crow;
    cpb0 = (scan_type==0) ? (size_t)s*80 : (size_t)(s/80)*4800 + (s%80);
    if (cv1){
      int s2 = s0 + crow + 8;
      cpb1 = (scan_type==0) ? (size_t)s2*80 : (size_t)(s2/80)*4800 + (s2%80);
    }
  }
  auto copy_gx = [&](int t, int buf){
    int toff = dir ? (T-1-t) : t;
    cpasync16(&gxs[buf][crow][cch*8],
              g_gxh + (cpb0 + (size_t)toff*pstride)*1024 + dir*512 + cch*8);
    if (cv1)
      cpasync16(&gxs[buf][crow+8][cch*8],
                g_gxh + (cpb1 + (size_t)toff*pstride)*1024 + dir*512 + cch*8);
    cp_commit();
  };

  // f16x2 pointwise: gates in half2, cell state fp32, tanh via MUFU f16x2
  auto rowupd = [&](const uint32_t* acc, int d, const __half (*gx)[520], int row, float* cst)->__half2{
    __half2 h05 = __float2half2_rn(0.5f);
    __half2 gi = __hadd2(*(__half2*)&acc[0*2+d], *(const __half2*)&gx[row][0*128+col]);
    __half2 gf = __hadd2(*(__half2*)&acc[1*2+d], *(const __half2*)&gx[row][1*128+col]);
    __half2 gg = __hadd2(*(__half2*)&acc[2*2+d], *(const __half2*)&gx[row][2*128+col]);
    __half2 go = __hadd2(*(__half2*)&acc[3*2+d], *(const __half2*)&gx[row][3*128+col]);
    float2 ti = __half22float2(tanh2(__hmul2(gi, h05)));
    float2 tf = __half22float2(tanh2(__hmul2(gf, h05)));
    float2 to = __half22float2(tanh2(__hmul2(go, h05)));
    float2 tg = __half22float2(tanh2(gg));
    float c0 = (0.5f*tf.x + 0.5f)*cst[0] + (0.5f*ti.x + 0.5f)*tg.x;
    float c1 = (0.5f*tf.y + 0.5f)*cst[1] + (0.5f*ti.y + 0.5f)*tg.y;
    cst[0] = c0; cst[1] = c1;
    float2 tc = __half22float2(tanh2(__floats2half2_rn(c0, c1)));
    return __floats2half2_rn((0.5f*to.x + 0.5f)*tc.x, (0.5f*to.y + 0.5f)*tc.y);
  };

  float cst1[2] = {0.f, 0.f}, cst2[2] = {0.f, 0.f};
  copy_gx(0, 0);

  for (int t=0; t<T; ++t){
    cp_wait<0>();
    __syncthreads();
    if (t+1 < T) copy_gx(t+1, (t+1)&1);

    uint32_t acc[8];   // [nt*2+d]
    #pragma unroll
    for (int i=0;i<8;i++) acc[i]=0u;
    const __half (*hb)[136] = hsm[t & 1];
    #pragma unroll
    for (int kc=0;kc<8;kc++){
      uint32_t a[4];
      ldsm4(a, &hb[lane & 15][kc*16 + (lane>>4)*8]);
      #pragma unroll
      for (int nt=0;nt<4;nt++)
        mma16816h(&acc[nt*2], a, bf[kc][nt][0], bf[kc][nt][1]);
    }

    const __half (*gx)[520] = gxs[t & 1];
    int toff = dir ? (T-1-t) : t;
    {
      __half2 hh = rowupd(acc, 0, gx, r, cst1);
      *(__half2*)&hsm[(t+1)&1][r][col] = hh;
      size_t pos1 = posbase1 + (size_t)toff * pstride;
      *(__half2*)&yout[pos1*256 + dir*128 + col] = hh;
    }
    if (act2){
      __half2 hh = rowupd(acc, 1, gx, r+8, cst2);
      *(__half2*)&hsm[(t+1)&1][r+8][col] = hh;
      size_t pos2 = posbase2 + (size_t)toff * pstride;
      *(__half2*)&yout[pos2*256 + dir*128 + col] = hh;
    }
  }
}

// ---------------- output head ----------------
__global__ __launch_bounds__(256) void k_conv_sig(
    int ysel, const float* __restrict__ cw, const float* __restrict__ cb){
  int tid = threadIdx.x, lane = tid & 31, wp = tid >> 5;
  const __half* Y = pick_x(ysel);
  float w[8];
  #pragma unroll
  for (int j=0;j<8;j++) w[j] = __ldg(&cw[lane*8 + j]);
  float b = __ldg(&cb[0]);
  #pragma unroll
  for (int it=0; it<4; ++it){
    int pos = blockIdx.x*32 + it*8 + wp;
    const __half* yp = Y + (size_t)pos*256 + lane*8;
    uint4 v = *(const uint4*)yp;
    const __half2* hv = (const __half2*)&v;
    float a = 0.f;
    #pragma unroll
    for (int j=0;j<4;j++){
      float2 f = __half22float2(hv[j]);
      a += f.x*w[2*j] + f.y*w[2*j+1];
    }
    #pragma unroll
    for (int d=16;d;d>>=1) a += __shfl_xor_sync(0xffffffffu, a, d);
    if (lane == 0) g_score[pos] = sigm(a + b);
  }
}

__global__ void k_upsample(float* __restrict__ out){
  int idx = blockIdx.x*blockDim.x + threadIdx.x;
  if (idx >= NB*480*640) return;
  int ox = idx % 640, oy = (idx/640) % 480, n = idx/(640*480);
  float sy = oy * (59.f/479.f);
  int iy = (int)sy; if (iy > 58) iy = 58;
  float ty = sy - (float)iy;
  float sx = ox * (79.f/639.f);
  int ix = (int)sx; if (ix > 78) ix = 78;
  float tx = sx - (float)ix;
  const float* sp = g_score + n*4800;
  float v00 = sp[iy*80+ix],     v01 = sp[iy*80+ix+1];
  float v10 = sp[(iy+1)*80+ix], v11 = sp[(iy+1)*80+ix+1];
  out[idx] = (v00*(1.f-ty)+v10*ty)*(1.f-tx) + (v01*(1.f-ty)+v11*ty)*tx;
}

// ---------------- launch ----------------
extern "C" void kernel_launch(void* const* d_in, const int* in_sizes, int n_in,
                              void* d_out, int out_size){
  const float* lf   = (const float*)d_in[0];
  const float* sc   = (const float*)d_in[1];
  const float* fc1w = (const float*)d_in[2];
  const float* fc1b = (const float*)d_in[3];
  const float* fcrw = (const float*)d_in[4];
  const float* fcrb = (const float*)d_in[5];
  const float* wih[4] = {(const float*)d_in[6], (const float*)d_in[9],
                         (const float*)d_in[12], (const float*)d_in[15]};
  const float* whh[4] = {(const float*)d_in[7], (const float*)d_in[10],
                         (const float*)d_in[13], (const float*)d_in[16]};
  const float* bb[4]  = {(const float*)d_in[8], (const float*)d_in[11],
                         (const float*)d_in[14], (const float*)d_in[17]};
  const float* cw = (const float*)d_in[18];
  const float* cb = (const float*)d_in[19];
  float* out = (float*)d_out;

  int bmoff[4] = {0, 512*1024, 768*1024, 1024*1024};

  cudaFuncSetAttribute(k_gemm_proj<1>, cudaFuncAttributeMaxDynamicSharedMemorySize, GEMM_SMEM);
  cudaFuncSetAttribute(k_gemm_proj<2>, cudaFuncAttributeMaxDynamicSharedMemorySize, GEMM_SMEM);

  // profiled = my idx 3 (global 5, offset +2 confirmed) -> k_scan L0
  k_prep_all<<<22624, 256>>>(sc, fc1w, fc1b, fcrw, fcrb,
                             wih[0], wih[1], wih[2], wih[3],
                             whh[0], whh[1], whh[2], whh[3], lf);                  // 0
  k_scproj_all<<<dim3(32,4), 256>>>(wih[0], wih[1], wih[2], wih[3]);               // 1
  k_gemm_proj<2><<<dim3(300,8), 256, GEMM_SMEM>>>(0, bmoff[0], bb[0], 0, 512, 0);  // 2
  k_scan<<<120, 512>>>(0, 1, 0, 80, 60, 8);                                        // 3 <- profiled

  k_gemm_proj<1><<<dim3(300,8), 256, GEMM_SMEM>>>(1, bmoff[1], bb[1], 8192, 256, 1);
  k_scan<<<128, 512>>>(1, 2, 1, 60, 64, 10);

  k_gemm_proj<1><<<dim3(300,8), 256, GEMM_SMEM>>>(2, bmoff[2], bb[2], 16384, 256, 0);
  k_scan<<<120, 512>>>(2, 1, 0, 80, 60, 8);

  k_gemm_proj<1><<<dim3(300,8), 256, GEMM_SMEM>>>(1, bmoff[3], bb[3], 24576, 256, 1);
  k_scan<<<128, 512>>>(3, 2, 1, 60, 64, 10);

  k_conv_sig<<<1200, 256>>>(2, cw, cb);
  k_upsample<<<(NB*480*640 + 255)/256, 256>>>(out);
}

// round 16
// speedup vs baseline: 1.1159x; 1.1159x over previous
#include <cuda_runtime.h>
#include <cuda_fp16.h>
#include <cstdint>

#define NB 8
#define HGT 60
#define WID 80
#define PP (NB*HGT*WID)   // 38400 positions

// ---------------- static scratch ----------------
__device__ __half g_x1[(size_t)PP*512];
__device__ __half g_ya[(size_t)PP*256];
__device__ __half g_yb[(size_t)PP*256];
__device__ __half g_gxh[(size_t)PP*1024];
__device__ __half g_bmat[(size_t)1280*1024];
__device__ __half g_wrec[(size_t)4*2*512*128];
__device__ float  g_scp[4*8*1024];
__device__ float  g_sc1[8*512];
__device__ float  g_scr[8*256];
__device__ float  g_score[PP];

// ---------------- helpers ----------------
__device__ __forceinline__ __half2 tanh2(__half2 x){
  uint32_t y, xi = *(uint32_t*)&x;
  asm("tanh.approx.f16x2 %0, %1;" : "=r"(y) : "r"(xi));
  return *(__half2*)&y;
}
__device__ __forceinline__ float sigm(float x){ return __fdividef(1.f, 1.f + __expf(-x)); }

__device__ __forceinline__ void ldsm4(uint32_t* r, const void* p){
  uint32_t a = (uint32_t)__cvta_generic_to_shared(p);
  asm volatile("ldmatrix.sync.aligned.m8n8.x4.shared.b16 {%0,%1,%2,%3}, [%4];\n"
    : "=r"(r[0]),"=r"(r[1]),"=r"(r[2]),"=r"(r[3]) : "r"(a));
}
__device__ __forceinline__ void ldsm4t(uint32_t* r, const void* p){
  uint32_t a = (uint32_t)__cvta_generic_to_shared(p);
  asm volatile("ldmatrix.sync.aligned.m8n8.x4.trans.shared.b16 {%0,%1,%2,%3}, [%4];\n"
    : "=r"(r[0]),"=r"(r[1]),"=r"(r[2]),"=r"(r[3]) : "r"(a));
}
// fp32-accum
__device__ __forceinline__ void mma16816(float* c, const uint32_t* a, uint32_t b0, uint32_t b1){
  asm volatile(
    "mma.sync.aligned.m16n8k16.row.col.f32.f16.f16.f32 "
    "{%0,%1,%2,%3}, {%4,%5,%6,%7}, {%8,%9}, {%0,%1,%2,%3};\n"
    : "+f"(c[0]), "+f"(c[1]), "+f"(c[2]), "+f"(c[3])
    : "r"(a[0]), "r"(a[1]), "r"(a[2]), "r"(a[3]), "r"(b0), "r"(b1));
}
// fp16-accum (double issue rate)
__device__ __forceinline__ void mma16816h(uint32_t* c, const uint32_t* a, uint32_t b0, uint32_t b1){
  asm volatile(
    "mma.sync.aligned.m16n8k16.row.col.f16.f16.f16.f16 "
    "{%0,%1}, {%2,%3,%4,%5}, {%6,%7}, {%0,%1};\n"
    : "+r"(c[0]), "+r"(c[1])
    : "r"(a[0]), "r"(a[1]), "r"(a[2]), "r"(a[3]), "r"(b0), "r"(b1));
}
__device__ __forceinline__ void cpasync16(void* smem, const void* g){
  uint32_t a = (uint32_t)__cvta_generic_to_shared(smem);
  asm volatile("cp.async.cg.shared.global [%0], [%1], 16;\n" :: "r"(a), "l"(g));
}
__device__ __forceinline__ void cp_commit(){ asm volatile("cp.async.commit_group;\n"); }
template<int N> __device__ __forceinline__ void cp_wait(){
  asm volatile("cp.async.wait_group %0;\n" :: "n"(N));
}
__device__ __forceinline__ const __half* pick_x(int s){
  return s==0 ? g_x1 : (s==1 ? g_ya : g_yb);
}
__device__ __forceinline__ __half* pick_y(int s){
  return s==1 ? g_ya : g_yb;
}

// ---------------- merged prep ----------------
__global__ __launch_bounds__(256) void k_prep_all(
    const float* __restrict__ scene,
    const float* __restrict__ fc1w, const float* __restrict__ fc1b,
    const float* __restrict__ fcrw, const float* __restrict__ fcrb,
    const float* __restrict__ w0, const float* __restrict__ w1,
    const float* __restrict__ w2, const float* __restrict__ w3,
    const float* __restrict__ h0, const float* __restrict__ h1,
    const float* __restrict__ h2, const float* __restrict__ h3,
    const float* __restrict__ lf){
  __shared__ float smu[32*33];
  const int b = blockIdx.x, tid = threadIdx.x;
  if (b < 96){
    float (*s)[128] = (float(*)[128])smu;
    int lane = tid & 31, wp = tid >> 5;
    for (int i = tid; i < 1024; i += 256) s[i>>7][i&127] = scene[i];
    __syncthreads();
    int o = b*8 + wp;
    const float* wrow; float bb; float* outp; int stride;
    if (o < 512){ wrow = fc1w + o*128; bb = fc1b[o]; outp = g_sc1 + o; stride = 512; }
    else { int oo = o-512; wrow = fcrw + oo*128; bb = fcrb[oo]; outp = g_scr + oo; stride = 256; }
    float q0 = wrow[lane], q1 = wrow[32+lane], q2 = wrow[64+lane], q3 = wrow[96+lane];
    #pragma unroll
    for (int n=0;n<8;n++){
      float p = q0*s[n][lane] + q1*s[n][32+lane] + q2*s[n][64+lane] + q3*s[n][96+lane];
      #pragma unroll
      for (int d=16;d;d>>=1) p += __shfl_xor_sync(0xffffffffu, p, d);
      if (lane == 0) outp[n*stride] = p + bb;
    }
  } else if (b < 1376){
    int id = b - 96, L, kx, cx;
    if (id < 512){ L = 0; kx = id >> 5; cx = id & 31; }
    else { id -= 512; L = 1 + id/256; int rr = id % 256; kx = rr >> 5; cx = rr & 31; }
    const int I = (L==0) ? 512 : 256;
    const float* wih = (L==0) ? w0 : (L==1) ? w1 : (L==2) ? w2 : w3;
    const size_t bmoff = (L==0) ? 0 : (size_t)(256 + 256*L)*1024;
    float (*tile)[33] = (float(*)[33])smu;
    int tx = tid & 31, ty = tid >> 5;
    int k0 = kx*32, c0 = cx*32;
    #pragma unroll
    for (int i=0;i<4;i++)
      tile[ty + i*8][tx] = wih[(size_t)(c0 + ty + i*8)*I + k0 + tx];
    __syncthreads();
    #pragma unroll
    for (int i=0;i<4;i++)
      g_bmat[bmoff + (size_t)(k0 + ty + i*8)*1024 + c0 + tx] = __float2half(tile[tx][ty + i*8]);
  } else if (b < 3424){
    int id = (b - 1376)*256 + tid;
    int L = id >> 17, r = id & 131071;
    const float* src = (L==0) ? h0 : (L==1) ? h1 : (L==2) ? h2 : h3;
    g_wrec[id] = __float2half(src[r]);
  } else {
    int id = b - 3424;
    int p0 = (id % 150)*32, c0 = ((id/150) & 15)*32, n = id/2400;
    float (*tile)[33] = (float(*)[33])smu;
    int tx = tid & 31, ty = tid >> 5;
    #pragma unroll
    for (int i=0;i<4;i++)
      tile[ty + i*8][tx] = lf[((size_t)(n*512 + c0 + ty + i*8))*4800 + p0 + tx];
    __syncthreads();
    #pragma unroll
    for (int i=0;i<4;i++)
      g_x1[((size_t)(n*4800 + p0 + ty + i*8))*512 + c0 + tx] = __float2half(tile[tx][ty + i*8]);
  }
}

// scene-context projection, all 4 layers
__global__ __launch_bounds__(256) void k_scproj_all(
    const float* __restrict__ w0, const float* __restrict__ w1,
    const float* __restrict__ w2, const float* __restrict__ w3){
  __shared__ float s[8*512];
  const int L = blockIdx.y;
  const int I = (L==0) ? 512 : 256;
  const float* wih = (L==0) ? w0 : (L==1) ? w1 : (L==2) ? w2 : w3;
  const float* scsrc = (L==0) ? g_sc1 : g_scr;
  int tid = threadIdx.x, lane = tid & 31, wp = tid >> 5;
  for (int i = tid; i < 8*I; i += 256) s[i] = scsrc[i];
  __syncthreads();
  for (int c = wp; c < 32; c += 8){
    int col = blockIdx.x*32 + c;
    const float* wr = wih + (size_t)col * I;
    float w[16];
    #pragma unroll
    for (int i=0;i<16;i++) w[i] = (i*32 < I) ? wr[lane + i*32] : 0.f;
    #pragma unroll
    for (int n=0;n<8;n++){
      float p = 0.f;
      #pragma unroll
      for (int i=0;i<16;i++) if (i*32 < I) p += w[i]*s[n*I + lane + i*32];
      #pragma unroll
      for (int d=16;d;d>>=1) p += __shfl_xor_sync(0xffffffffu, p, d);
      if (lane == 0) g_scp[L*8192 + n*1024 + col] = p;
    }
  }
}

// ---------------- input-projection GEMM (templated accumulator precision) ----------------
#define AS_OFF(buf) ((buf)*9216)
#define BS_OFF(buf) (18432 + (buf)*8704)
#define GEMM_SMEM ((18432 + 2*8704)*2)

template<int HACC>
__global__ __launch_bounds__(256) void k_gemm_proj(
    int xsel, int bmoff, const float* __restrict__ bias, int scpoff,
    int I, int scan_type){
  extern __shared__ __half sm[];
  const __half* __restrict__ X = pick_x(xsel);
  const __half* __restrict__ Bm = g_bmat + (size_t)bmoff;
  const int tid = threadIdx.x, lane = tid & 31, wp = tid >> 5;
  const int wm = wp & 3, wn = wp >> 2;
  const int m0 = blockIdx.x * 128, n0 = blockIdx.y * 128;
  const int nch = I >> 6;
  float acc[HACC ? 1 : 2][8][4];
  uint32_t acch[HACC ? 2 : 1][8][2];
  #pragma unroll
  for (int a=0;a<(HACC?1:2);a++)
    #pragma unroll
    for (int b=0;b<8;b++)
      #pragma unroll
      for (int c=0;c<4;c++) acc[a][b][c]=0.f;
  #pragma unroll
  for (int a=0;a<(HACC?2:1);a++)
    #pragma unroll
    for (int b=0;b<8;b++){ acch[a][b][0]=0u; acch[a][b][1]=0u; }

  auto stage = [&](int c, int buf){
    int k0 = c*64;
    __half* as = sm + AS_OFF(buf);
    __half* bs = sm + BS_OFF(buf);
    #pragma unroll
    for (int i=0;i<4;i++){
      int idx = tid + i*256;
      int r = idx >> 3, cb = (idx & 7) * 8;
      cpasync16(&as[r*72 + cb], &X[(size_t)(m0 + r) * I + k0 + cb]);
    }
    #pragma unroll
    for (int i=0;i<4;i++){
      int idx = tid + i*256;
      int r = idx >> 4, cb = (idx & 15) * 8;
      cpasync16(&bs[r*136 + cb], &Bm[(size_t)(k0 + r) * 1024 + n0 + cb]);
    }
    cp_commit();
  };

  stage(0, 0);
  if (nch > 1) stage(1, 1);

  for (int c = 0; c < nch; ++c){
    if (c+1 < nch) cp_wait<1>(); else cp_wait<0>();
    __syncthreads();
    const __half* as = sm + AS_OFF(c & 1);
    const __half* bs = sm + BS_OFF(c & 1);
    #pragma unroll
    for (int kc=0;kc<4;kc++){
      uint32_t a[2][4];
      #pragma unroll
      for (int mt=0;mt<2;mt++){
        int row = wm*32 + mt*16 + ((lane>>3)&1)*8 + (lane&7);
        int col = kc*16 + (lane>>4)*8;
        ldsm4(a[mt], &as[row*72 + col]);
      }
      #pragma unroll
      for (int p=0;p<4;p++){
        uint32_t b[4];
        int row = kc*16 + ((lane>>3)&1)*8 + (lane&7);
        int col = wn*64 + p*16 + (lane>>4)*8;
        ldsm4t(b, &bs[row*136 + col]);
        #pragma unroll
        for (int mt=0;mt<2;mt++){
          if (HACC){
            mma16816h(acch[mt][2*p],   a[mt], b[0], b[1]);
            mma16816h(acch[mt][2*p+1], a[mt], b[2], b[3]);
          } else {
            mma16816(acc[mt][2*p],   a[mt], b[0], b[1]);
            mma16816(acc[mt][2*p+1], a[mt], b[2], b[3]);
          }
        }
      }
    }
    __syncthreads();
    if (c+2 < nch) stage(c+2, c & 1);
  }

  const int r0 = lane >> 2, cc0 = (lane & 3) * 2;
  const float* scp = g_scp + scpoff;
  #pragma unroll
  for (int mt=0; mt<2; mt++)
    #pragma unroll
    for (int hf=0; hf<2; hf++){
      int m = m0 + wm*32 + mt*16 + hf*8 + r0;
      bool bnd;
      if (scan_type==0){ int wv = m % 80; bnd = (wv==0)||(wv==79); }
      else { int hv = (m/80)%60; bnd = (hv==0)||(hv==59); }
      const float* sp = scp + (m/4800)*1024;
      #pragma unroll
      for (int nt=0;nt<8;nt++){
        int c = n0 + wn*64 + nt*8 + cc0;
        float v0, v1;
        if (HACC){
          float2 f = __half22float2(*(__half2*)&acch[mt][nt][hf]);
          v0 = f.x; v1 = f.y;
        } else {
          v0 = acc[mt][nt][hf*2+0]; v1 = acc[mt][nt][hf*2+1];
        }
        v0 += bias[c]; v1 += bias[c+1];
        if (bnd){ v0 += sp[c]; v1 += sp[c+1]; }
        *(__half2*)&g_gxh[(size_t)m*1024 + c] = __floats2half2_rn(v0, v1);
      }
    }
}

// ---------------- persistent BLSTM scan: cp.async gx staging + f16x2 activations ----------------
__global__ __launch_bounds__(512) void k_scan(
    int layer, int ysel, int scan_type, int T, int bpd, int S){
  __shared__ __half hsm[2][16][136];
  __shared__ __half gxs[2][16][520];
  __half* __restrict__ yout = pick_y(ysel);
  const int tid = threadIdx.x, lane = tid & 31, wp = tid >> 5;
  const int dir = blockIdx.x / bpd;
  const int s0 = (blockIdx.x % bpd) * S;
  const __half* __restrict__ wd = g_wrec + (size_t)layer*131072 + (size_t)dir*65536;

  uint32_t bf[8][4][2];
  #pragma unroll
  for (int kc=0;kc<8;kc++)
    #pragma unroll
    for (int nt=0;nt<4;nt++){
      int n = nt*128 + wp*8 + (lane>>2);
      int k = kc*16 + (lane&3)*2;
      bf[kc][nt][0] = *(const uint32_t*)&wd[(size_t)n*128 + k];
      bf[kc][nt][1] = *(const uint32_t*)&wd[(size_t)n*128 + k + 8];
    }

  for (int i = tid; i < 2*16*136; i += 512) ((__half*)hsm)[i] = __ushort_as_half((unsigned short)0);

  const int r  = lane >> 2;
  const int ul = (lane & 3) * 2;
  const int col = wp*8 + ul;
  const bool act2 = (r + 8) < S;
  int pstride = (scan_type == 0) ? 1 : 80;
  size_t posbase1 = 0, posbase2 = 0;
  {
    int s = s0 + r;
    posbase1 = (scan_type==0) ? (size_t)s*80 : (size_t)(s/80)*4800 + (s%80);
    if (act2){
      int s2 = s0 + r + 8;
      posbase2 = (scan_type==0) ? (size_t)s2*80 : (size_t)(s2/80)*4800 + (s2%80);
    }
  }
  const int crow = tid >> 6;
  const int cch  = tid & 63;
  const bool cv1 = (crow + 8) < S;
  size_t cpb0, cpb1 = 0;
  {
    int s = s0 + crow;
    cpb0 = (scan_type==0) ? (size_t)s*80 : (size_t)(s/80)*4800 + (s%80);
    if (cv1){
      int s2 = s0 + crow + 8;
      cpb1 = (scan_type==0) ? (size_t)s2*80 : (size_t)(s2/80)*4800 + (s2%80);
    }
  }
  auto copy_gx = [&](int t, int buf){
    int toff = dir ? (T-1-t) : t;
    cpasync16(&gxs[buf][crow][cch*8],
              g_gxh + (cpb0 + (size_t)toff*pstride)*1024 + dir*512 + cch*8);
    if (cv1)
      cpasync16(&gxs[buf][crow+8][cch*8],
                g_gxh + (cpb1 + (size_t)toff*pstride)*1024 + dir*512 + cch*8);
    cp_commit();
  };

  float cst1[2] = {0.f, 0.f}, cst2[2] = {0.f, 0.f};
  copy_gx(0, 0);

  for (int t=0; t<T; ++t){
    cp_wait<0>();
    __syncthreads();
    if (t+1 < T) copy_gx(t+1, (t+1)&1);

    uint32_t acc[4][2];
    #pragma unroll
    for (int nt=0;nt<4;nt++){ acc[nt][0]=0u; acc[nt][1]=0u; }
    const __half (*hb)[136] = hsm[t & 1];
    #pragma unroll
    for (int kc=0;kc<8;kc++){
      uint32_t a[4];
      ldsm4(a, &hb[lane & 15][kc*16 + (lane>>4)*8]);
      #pragma unroll
      for (int nt=0;nt<4;nt++)
        mma16816h(acc[nt], a, bf[kc][nt][0], bf[kc][nt][1]);
    }

    const __half (*gx)[520] = gxs[t & 1];
    int toff = dir ? (T-1-t) : t;
    const __half2 h05 = __float2half2_rn(0.5f);
    // row r (d=0)
    {
      __half2 gi = __hadd2(*(__half2*)&acc[0][0], *(const __half2*)&gx[r][0*128+col]);
      __half2 gf = __hadd2(*(__half2*)&acc[1][0], *(const __half2*)&gx[r][1*128+col]);
      __half2 gg = __hadd2(*(__half2*)&acc[2][0], *(const __half2*)&gx[r][2*128+col]);
      __half2 go = __hadd2(*(__half2*)&acc[3][0], *(const __half2*)&gx[r][3*128+col]);
      float2 ti = __half22float2(tanh2(__hmul2(gi, h05)));
      float2 tf = __half22float2(tanh2(__hmul2(gf, h05)));
      float2 to = __half22float2(tanh2(__hmul2(go, h05)));
      float2 tg = __half22float2(tanh2(gg));
      float c0 = (0.5f*tf.x + 0.5f)*cst1[0] + (0.5f*ti.x + 0.5f)*tg.x;
      float c1 = (0.5f*tf.y + 0.5f)*cst1[1] + (0.5f*ti.y + 0.5f)*tg.y;
      cst1[0] = c0; cst1[1] = c1;
      float2 tc = __half22float2(tanh2(__floats2half2_rn(c0, c1)));
      __half2 hh = __floats2half2_rn((0.5f*to.x + 0.5f)*tc.x, (0.5f*to.y + 0.5f)*tc.y);
      *(__half2*)&hsm[(t+1)&1][r][col] = hh;
      size_t pos1 = posbase1 + (size_t)toff * pstride;
      *(__half2*)&yout[pos1*256 + dir*128 + col] = hh;
    }
    // row r+8 (d=1)
    if (act2){
      __half2 gi = __hadd2(*(__half2*)&acc[0][1], *(const __half2*)&gx[r+8][0*128+col]);
      __half2 gf = __hadd2(*(__half2*)&acc[1][1], *(const __half2*)&gx[r+8][1*128+col]);
      __half2 gg = __hadd2(*(__half2*)&acc[2][1], *(const __half2*)&gx[r+8][2*128+col]);
      __half2 go = __hadd2(*(__half2*)&acc[3][1], *(const __half2*)&gx[r+8][3*128+col]);
      float2 ti = __half22float2(tanh2(__hmul2(gi, h05)));
      float2 tf = __half22float2(tanh2(__hmul2(gf, h05)));
      float2 to = __half22float2(tanh2(__hmul2(go, h05)));
      float2 tg = __half22float2(tanh2(gg));
      float c0 = (0.5f*tf.x + 0.5f)*cst2[0] + (0.5f*ti.x + 0.5f)*tg.x;
      float c1 = (0.5f*tf.y + 0.5f)*cst2[1] + (0.5f*ti.y + 0.5f)*tg.y;
      cst2[0] = c0; cst2[1] = c1;
      float2 tc = __half22float2(tanh2(__floats2half2_rn(c0, c1)));
      __half2 hh = __floats2half2_rn((0.5f*to.x + 0.5f)*tc.x, (0.5f*to.y + 0.5f)*tc.y);
      *(__half2*)&hsm[(t+1)&1][r+8][col] = hh;
      size_t pos2 = posbase2 + (size_t)toff * pstride;
      *(__half2*)&yout[pos2*256 + dir*128 + col] = hh;
    }
  }
}

// ---------------- output head ----------------
__global__ __launch_bounds__(256) void k_conv_sig(
    int ysel, const float* __restrict__ cw, const float* __restrict__ cb){
  int tid = threadIdx.x, lane = tid & 31, wp = tid >> 5;
  const __half* Y = pick_x(ysel);
  float w[8];
  #pragma unroll
  for (int j=0;j<8;j++) w[j] = __ldg(&cw[lane*8 + j]);
  float b = __ldg(&cb[0]);
  #pragma unroll
  for (int it=0; it<4; ++it){
    int pos = blockIdx.x*32 + it*8 + wp;
    const __half* yp = Y + (size_t)pos*256 + lane*8;
    uint4 v = *(const uint4*)yp;
    const __half2* hv = (const __half2*)&v;
    float a = 0.f;
    #pragma unroll
    for (int j=0;j<4;j++){
      float2 f = __half22float2(hv[j]);
      a += f.x*w[2*j] + f.y*w[2*j+1];
    }
    #pragma unroll
    for (int d=16;d;d>>=1) a += __shfl_xor_sync(0xffffffffu, a, d);
    if (lane == 0) g_score[pos] = sigm(a + b);
  }
}

__global__ void k_upsample(float* __restrict__ out){
  int idx = blockIdx.x*blockDim.x + threadIdx.x;
  if (idx >= NB*480*640) return;
  int ox = idx % 640, oy = (idx/640) % 480, n = idx/(640*480);
  float sy = oy * (59.f/479.f);
  int iy = (int)sy; if (iy > 58) iy = 58;
  float ty = sy - (float)iy;
  float sx = ox * (79.f/639.f);
  int ix = (int)sx; if (ix > 78) ix = 78;
  float tx = sx - (float)ix;
  const float* sp = g_score + n*4800;
  float v00 = sp[iy*80+ix],     v01 = sp[iy*80+ix+1];
  float v10 = sp[(iy+1)*80+ix], v11 = sp[(iy+1)*80+ix+1];
  out[idx] = (v00*(1.f-ty)+v10*ty)*(1.f-tx) + (v01*(1.f-ty)+v11*ty)*tx;
}

// ---------------- launch ----------------
extern "C" void kernel_launch(void* const* d_in, const int* in_sizes, int n_in,
                              void* d_out, int out_size){
  const float* lf   = (const float*)d_in[0];
  const float* sc   = (const float*)d_in[1];
  const float* fc1w = (const float*)d_in[2];
  const float* fc1b = (const float*)d_in[3];
  const float* fcrw = (const float*)d_in[4];
  const float* fcrb = (const float*)d_in[5];
  const float* wih[4] = {(const float*)d_in[6], (const float*)d_in[9],
                         (const float*)d_in[12], (const float*)d_in[15]};
  const float* whh[4] = {(const float*)d_in[7], (const float*)d_in[10],
                         (const float*)d_in[13], (const float*)d_in[16]};
  const float* bb[4]  = {(const float*)d_in[8], (const float*)d_in[11],
                         (const float*)d_in[14], (const float*)d_in[17]};
  const float* cw = (const float*)d_in[18];
  const float* cb = (const float*)d_in[19];
  float* out = (float*)d_out;

  int bmoff[4] = {0, 512*1024, 768*1024, 1024*1024};

  cudaFuncSetAttribute(k_gemm_proj<0>, cudaFuncAttributeMaxDynamicSharedMemorySize, GEMM_SMEM);
  cudaFuncSetAttribute(k_gemm_proj<1>, cudaFuncAttributeMaxDynamicSharedMemorySize, GEMM_SMEM);

  // profiled = my idx 3 (global 5, offset +2 confirmed) -> k_scan L0
  k_prep_all<<<22624, 256>>>(sc, fc1w, fc1b, fcrw, fcrb,
                             wih[0], wih[1], wih[2], wih[3],
                             whh[0], whh[1], whh[2], whh[3], lf);                  // 0
  k_scproj_all<<<dim3(32,4), 256>>>(wih[0], wih[1], wih[2], wih[3]);               // 1
  k_gemm_proj<0><<<dim3(300,8), 256, GEMM_SMEM>>>(0, bmoff[0], bb[0], 0, 512, 0);  // 2
  k_scan<<<120, 512>>>(0, 1, 0, 80, 60, 8);                                        // 3 <- profiled

  k_gemm_proj<1><<<dim3(300,8), 256, GEMM_SMEM>>>(1, bmoff[1], bb[1], 8192, 256, 1);
  k_scan<<<128, 512>>>(1, 2, 1, 60, 64, 10);

  k_gemm_proj<1><<<dim3(300,8), 256, GEMM_SMEM>>>(2, bmoff[2], bb[2], 16384, 256, 0);
  k_scan<<<120, 512>>>(2, 1, 0, 80, 60, 8);

  k_gemm_proj<1><<<dim3(300,8), 256, GEMM_SMEM>>>(1, bmoff[3], bb[3], 24576, 256, 1);
  k_scan<<<128, 512>>>(3, 2, 1, 60, 64, 10);

  k_conv_sig<<<1200, 256>>>(2, cw, cb);
  k_upsample<<<(NB*480*640 + 255)/256, 256>>>(out);
}